// round 2
// baseline (speedup 1.0000x reference)
#include <cuda_runtime.h>

#define N_NODES 50000
#define D_FEAT  128
#define N_EDGES 800000
#define ROW_F4  (D_FEAT / 4)   // 32 float4 per row

// Scratch (allocation-free rule: __device__ globals)
__device__ float4 g_pooled[N_NODES * ROW_F4];   // 25.6 MB, GEMM input
__device__ int    g_hist_out[N_NODES];
__device__ int    g_hist_in[N_NODES];
__device__ int    g_offsets[N_NODES + 1];       // CSR row offsets (by target)
__device__ int    g_cursor[N_NODES];
__device__ int    g_sorted_src[N_EDGES];        // sources grouped by target
__device__ float  g_sscale[N_NODES];            // rsqrt(max(out_deg,1))

// ---------------------------------------------------------------------------
// K0: zero the two int histograms (only thing that needs zeroing now)
// ---------------------------------------------------------------------------
__global__ void zero_kernel() {
    int i = blockIdx.x * blockDim.x + threadIdx.x;
    int stride = gridDim.x * blockDim.x;
    for (int j = i; j < N_NODES; j += stride) {
        g_hist_out[j] = 0;
        g_hist_in[j]  = 0;
    }
}

// ---------------------------------------------------------------------------
// K1: degree histograms
// ---------------------------------------------------------------------------
__global__ void hist_kernel(const int* __restrict__ src,
                            const int* __restrict__ tgt) {
    int e = blockIdx.x * blockDim.x + threadIdx.x;
    if (e < N_EDGES) {
        atomicAdd(&g_hist_out[src[e]], 1);
        atomicAdd(&g_hist_in[tgt[e]], 1);
    }
}

// ---------------------------------------------------------------------------
// K2: single-block exclusive prefix scan of in-degrees -> CSR offsets.
// Also precompute sender scales.
// ---------------------------------------------------------------------------
__global__ __launch_bounds__(1024) void scan_kernel() {
    __shared__ int sh_w[32];     // warp totals
    __shared__ int sh_off[32];   // exclusive warp offsets
    __shared__ int sh_total;

    const int tid  = threadIdx.x;
    const int lane = tid & 31;
    const int w    = tid >> 5;
    int carry = 0;

    for (int base = 0; base < N_NODES; base += 1024) {
        int i = base + tid;
        int v = (i < N_NODES) ? g_hist_in[i] : 0;

        // warp inclusive scan
        int incl = v;
#pragma unroll
        for (int o = 1; o < 32; o <<= 1) {
            int n = __shfl_up_sync(0xFFFFFFFFu, incl, o);
            if (lane >= o) incl += n;
        }
        if (lane == 31) sh_w[w] = incl;
        __syncthreads();
        if (tid < 32) {
            int t = sh_w[tid];
            int p = t;
#pragma unroll
            for (int o = 1; o < 32; o <<= 1) {
                int n = __shfl_up_sync(0xFFFFFFFFu, p, o);
                if (tid >= o) p += n;
            }
            sh_off[tid] = p - t;
            if (tid == 31) sh_total = p;
        }
        __syncthreads();
        int excl = carry + sh_off[w] + incl - v;
        if (i < N_NODES) {
            g_offsets[i] = excl;
            g_cursor[i]  = excl;
            g_sscale[i]  = rsqrtf(fmaxf((float)g_hist_out[i], 1.0f));
        }
        carry += sh_total;
        // next iteration's first __syncthreads protects sh_off/sh_total reuse
    }
    if (tid == 0) g_offsets[N_NODES] = carry;   // == N_EDGES
}

// ---------------------------------------------------------------------------
// K3: counting-sort scatter — group edge sources by target node.
// ---------------------------------------------------------------------------
__global__ void sort_kernel(const int* __restrict__ src,
                            const int* __restrict__ tgt) {
    int e = blockIdx.x * blockDim.x + threadIdx.x;
    if (e < N_EDGES) {
        int pos = atomicAdd(&g_cursor[tgt[e]], 1);
        g_sorted_src[pos] = src[e];
    }
}

// ---------------------------------------------------------------------------
// K4: per-node gather-accumulate. One warp per target node, lane = float4
// index. Sender scale folded per edge, receiver scale folded on write.
// No atomics; pooled written exactly once.
// ---------------------------------------------------------------------------
__global__ __launch_bounds__(256) void gather_kernel(
        const float4* __restrict__ x) {
    int t    = (blockIdx.x * blockDim.x + threadIdx.x) >> 5;
    int lane = threadIdx.x & 31;
    if (t >= N_NODES) return;

    int start = g_offsets[t];
    int end   = g_offsets[t + 1];

    float4 acc = make_float4(0.f, 0.f, 0.f, 0.f);
#pragma unroll 4
    for (int j = start; j < end; ++j) {
        int   s  = __ldg(&g_sorted_src[j]);
        float sc = __ldg(&g_sscale[s]);
        float4 v = __ldg(&x[s * ROW_F4 + lane]);
        acc.x = fmaf(sc, v.x, acc.x);
        acc.y = fmaf(sc, v.y, acc.y);
        acc.z = fmaf(sc, v.z, acc.z);
        acc.w = fmaf(sc, v.w, acc.w);
    }
    float rsc = rsqrtf(fmaxf((float)(end - start), 1.0f));
    acc.x *= rsc; acc.y *= rsc; acc.z *= rsc; acc.w *= rsc;
    g_pooled[t * ROW_F4 + lane] = acc;
}

// ---------------------------------------------------------------------------
// K5: out = relu( pooled @ W + b ).  Full-K single-stage smem GEMM:
// 128-row x 128-col tile, entire A tile (64KB) + entire W (64KB) staged once,
// one barrier, then 128 k-steps vectorized x4. 512 threads, 8x4 micro-tile.
// ---------------------------------------------------------------------------
#define G_ROWS 128

__global__ __launch_bounds__(512) void gemm_kernel(
        const float4* __restrict__ W4,    // [128*32] row-major (k, j/4)
        const float4* __restrict__ b4,    // [32]
        float4* __restrict__ out) {       // [N_NODES * 32]
    extern __shared__ float4 sm4[];
    float4* As4 = sm4;                    // [128][32]  (row, k/4)
    float4* Ws4 = sm4 + G_ROWS * ROW_F4;  // [128][32]  (k, j/4)

    const int tid = threadIdx.x;
    const int tx  = tid & 31;        // col group: cols tx*4 .. tx*4+3
    const int ty  = tid >> 5;        // row group: rows ty*8 .. ty*8+7
    const int row_base = blockIdx.x * G_ROWS;

    // stage A tile + W (4096 float4 each; 512 threads x 8)
#pragma unroll
    for (int pass = 0; pass < 8; pass++) {
        int idx = pass * 512 + tid;      // 0..4095
        int r   = idx >> 5;              // 0..127
        int c   = idx & 31;              // 0..31
        int grow = row_base + r;
        float4 v = make_float4(0.f, 0.f, 0.f, 0.f);
        if (grow < N_NODES) v = g_pooled[grow * ROW_F4 + c];
        As4[idx] = v;
        Ws4[idx] = __ldg(&W4[idx]);
    }
    __syncthreads();

    float4 acc[8];
#pragma unroll
    for (int i = 0; i < 8; i++) acc[i] = make_float4(0.f, 0.f, 0.f, 0.f);

#pragma unroll 1
    for (int k4 = 0; k4 < 32; k4++) {
        float4 w0 = Ws4[(4 * k4 + 0) * 32 + tx];
        float4 w1 = Ws4[(4 * k4 + 1) * 32 + tx];
        float4 w2 = Ws4[(4 * k4 + 2) * 32 + tx];
        float4 w3 = Ws4[(4 * k4 + 3) * 32 + tx];
        float4 a[8];
#pragma unroll
        for (int i = 0; i < 8; i++)
            a[i] = As4[(ty * 8 + i) * 32 + k4];   // warp broadcast
#pragma unroll
        for (int i = 0; i < 8; i++) {
            acc[i].x = fmaf(a[i].x, w0.x, acc[i].x);
            acc[i].y = fmaf(a[i].x, w0.y, acc[i].y);
            acc[i].z = fmaf(a[i].x, w0.z, acc[i].z);
            acc[i].w = fmaf(a[i].x, w0.w, acc[i].w);
            acc[i].x = fmaf(a[i].y, w1.x, acc[i].x);
            acc[i].y = fmaf(a[i].y, w1.y, acc[i].y);
            acc[i].z = fmaf(a[i].y, w1.z, acc[i].z);
            acc[i].w = fmaf(a[i].y, w1.w, acc[i].w);
            acc[i].x = fmaf(a[i].z, w2.x, acc[i].x);
            acc[i].y = fmaf(a[i].z, w2.y, acc[i].y);
            acc[i].z = fmaf(a[i].z, w2.z, acc[i].z);
            acc[i].w = fmaf(a[i].z, w2.w, acc[i].w);
            acc[i].x = fmaf(a[i].w, w3.x, acc[i].x);
            acc[i].y = fmaf(a[i].w, w3.y, acc[i].y);
            acc[i].z = fmaf(a[i].w, w3.z, acc[i].z);
            acc[i].w = fmaf(a[i].w, w3.w, acc[i].w);
        }
    }

    // epilogue: bias + relu
    float4 bias = __ldg(&b4[tx]);
#pragma unroll
    for (int i = 0; i < 8; i++) {
        int r = row_base + ty * 8 + i;
        if (r >= N_NODES) continue;
        float4 o;
        o.x = fmaxf(acc[i].x + bias.x, 0.f);
        o.y = fmaxf(acc[i].y + bias.y, 0.f);
        o.z = fmaxf(acc[i].z + bias.z, 0.f);
        o.w = fmaxf(acc[i].w + bias.w, 0.f);
        out[r * ROW_F4 + tx] = o;
    }
}

// ---------------------------------------------------------------------------
// Inputs (metadata order): x [N,D] f32, source [E] i32, target [E] i32,
// W [D,U] f32, b [U] f32. Output: [N, U] f32.
// ---------------------------------------------------------------------------
extern "C" void kernel_launch(void* const* d_in, const int* in_sizes, int n_in,
                              void* d_out, int out_size) {
    const float4* x   = (const float4*)d_in[0];
    const int*    src = (const int*)d_in[1];
    const int*    tgt = (const int*)d_in[2];
    const float4* W4  = (const float4*)d_in[3];
    const float4* b   = (const float4*)d_in[4];
    float4* out = (float4*)d_out;

    const int GEMM_SMEM = 2 * G_ROWS * D_FEAT * (int)sizeof(float);  // 128 KB
    cudaFuncSetAttribute(gemm_kernel,
                         cudaFuncAttributeMaxDynamicSharedMemorySize, GEMM_SMEM);

    zero_kernel<<<256, 256>>>();
    hist_kernel<<<(N_EDGES + 255) / 256, 256>>>(src, tgt);
    scan_kernel<<<1, 1024>>>();
    sort_kernel<<<(N_EDGES + 255) / 256, 256>>>(src, tgt);
    gather_kernel<<<(N_NODES + 7) / 8, 256>>>(x);
    gemm_kernel<<<(N_NODES + G_ROWS - 1) / G_ROWS, 512, GEMM_SMEM>>>(W4, b, out);
}

// round 3
// speedup vs baseline: 1.5586x; 1.5586x over previous
#include <cuda_runtime.h>
#include <cstdint>

#define N_NODES 50000
#define D_FEAT  128
#define N_EDGES 800000
#define ROW_F4  32

// Scratch (__device__ globals — allocation-free rule)
__device__ float4 g_pooled[N_NODES * ROW_F4];   // 25.6 MB, GEMM input
__device__ int    g_hist_out[N_NODES];
__device__ int    g_hist_in[N_NODES];
__device__ int    g_start[N_NODES];
__device__ int    g_cursor[N_NODES];
__device__ int    g_sorted_src[N_EDGES];
__device__ float  g_sscale[N_NODES];
__device__ int    g_counter;

// ---------------------------------------------------------------------------
// K0: zero histograms + chunk counter
// ---------------------------------------------------------------------------
__global__ void zero_kernel() {
    int i = blockIdx.x * blockDim.x + threadIdx.x;
    int stride = gridDim.x * blockDim.x;
    for (int j = i; j < N_NODES; j += stride) {
        g_hist_out[j] = 0;
        g_hist_in[j]  = 0;
    }
    if (i == 0) g_counter = 0;
}

// ---------------------------------------------------------------------------
// K1: degree histograms (4 edges/thread for MLP)
// ---------------------------------------------------------------------------
__global__ void hist_kernel(const int* __restrict__ src,
                            const int* __restrict__ tgt) {
    const int T = N_EDGES / 4;
    int t = blockIdx.x * blockDim.x + threadIdx.x;
    if (t >= T) return;
#pragma unroll
    for (int u = 0; u < 4; u++) {
        int e = t + u * T;
        atomicAdd(&g_hist_out[__ldg(&src[e])], 1);
        atomicAdd(&g_hist_in[__ldg(&tgt[e])], 1);
    }
}

// ---------------------------------------------------------------------------
// K2: chunk assignment (replaces prefix scan — group order is irrelevant).
// Warp-aggregated atomicAdd on a global counter hands each node a contiguous
// slice of g_sorted_src. Also precompute sender scales.
// ---------------------------------------------------------------------------
__global__ void chunk_kernel() {
    int i    = blockIdx.x * blockDim.x + threadIdx.x;
    int lane = threadIdx.x & 31;
    int deg  = (i < N_NODES) ? g_hist_in[i] : 0;

    int incl = deg;
#pragma unroll
    for (int o = 1; o < 32; o <<= 1) {
        int n = __shfl_up_sync(0xFFFFFFFFu, incl, o);
        if (lane >= o) incl += n;
    }
    int total = __shfl_sync(0xFFFFFFFFu, incl, 31);
    int base = 0;
    if (lane == 31) base = atomicAdd(&g_counter, total);
    base = __shfl_sync(0xFFFFFFFFu, base, 31);

    if (i < N_NODES) {
        int st = base + incl - deg;
        g_start[i]  = st;
        g_cursor[i] = st;
        g_sscale[i] = rsqrtf(fmaxf((float)g_hist_out[i], 1.0f));
    }
}

// ---------------------------------------------------------------------------
// K3: counting-sort scatter, 4 independent edges per thread (MLP=4)
// ---------------------------------------------------------------------------
__global__ void sort_kernel(const int* __restrict__ src,
                            const int* __restrict__ tgt) {
    const int T = N_EDGES / 4;
    int t = blockIdx.x * blockDim.x + threadIdx.x;
    if (t >= T) return;
    int e0 = t, e1 = t + T, e2 = t + 2 * T, e3 = t + 3 * T;
    int t0 = __ldg(&tgt[e0]), t1 = __ldg(&tgt[e1]);
    int t2 = __ldg(&tgt[e2]), t3 = __ldg(&tgt[e3]);
    int s0 = __ldg(&src[e0]), s1 = __ldg(&src[e1]);
    int s2 = __ldg(&src[e2]), s3 = __ldg(&src[e3]);
    int p0 = atomicAdd(&g_cursor[t0], 1);
    int p1 = atomicAdd(&g_cursor[t1], 1);
    int p2 = atomicAdd(&g_cursor[t2], 1);
    int p3 = atomicAdd(&g_cursor[t3], 1);
    g_sorted_src[p0] = s0;
    g_sorted_src[p1] = s1;
    g_sorted_src[p2] = s2;
    g_sorted_src[p3] = s3;
}

// ---------------------------------------------------------------------------
// K4: per-node gather-accumulate. One warp per target node, lane = float4.
// Sender scale per edge, receiver scale folded on the single write.
// ---------------------------------------------------------------------------
__global__ __launch_bounds__(256) void gather_kernel(
        const float4* __restrict__ x) {
    int t    = (blockIdx.x * blockDim.x + threadIdx.x) >> 5;
    int lane = threadIdx.x & 31;
    if (t >= N_NODES) return;

    int start = __ldg(&g_start[t]);
    int deg   = __ldg(&g_hist_in[t]);

    float4 acc = make_float4(0.f, 0.f, 0.f, 0.f);
#pragma unroll 4
    for (int j = start; j < start + deg; ++j) {
        int   s  = __ldg(&g_sorted_src[j]);
        float sc = __ldg(&g_sscale[s]);
        float4 v = __ldg(&x[s * ROW_F4 + lane]);
        acc.x = fmaf(sc, v.x, acc.x);
        acc.y = fmaf(sc, v.y, acc.y);
        acc.z = fmaf(sc, v.z, acc.z);
        acc.w = fmaf(sc, v.w, acc.w);
    }
    float rsc = rsqrtf(fmaxf((float)deg, 1.0f));
    acc.x *= rsc; acc.y *= rsc; acc.z *= rsc; acc.w *= rsc;
    g_pooled[t * ROW_F4 + lane] = acc;
}

// ---------------------------------------------------------------------------
// K5: out = relu( pooled @ W + b ) via tf32 mma.sync with 3-term split:
//   D = Ahi@Whi + Ahi@Wlo + Alo@Whi   (dropped Alo@Wlo ~ 2^-22 relative)
// Block: 256 thr (8 warps), tile 128x128, full K=128 smem-resident.
// Warp tile: 32 rows x 64 cols (2 m16 slabs x 8 n8 tiles), 16 k-steps.
// ---------------------------------------------------------------------------
#define AS_STRIDE 132   // floats; (4*quad + tq) mod 32 unique -> conflict-free
#define WS_STRIDE 136   // floats; (8*tq + quad) mod 32 unique -> conflict-free
#define GEMM_SMEM ((128 * AS_STRIDE + 2 * 128 * WS_STRIDE) * (int)sizeof(float))

__device__ __forceinline__ void tf32_split(float a, uint32_t& hi, uint32_t& lo) {
    uint32_t h;
    asm("cvt.rna.tf32.f32 %0, %1;" : "=r"(h) : "f"(a));
    float r = a - __uint_as_float(h);
    uint32_t l;
    asm("cvt.rna.tf32.f32 %0, %1;" : "=r"(l) : "f"(r));
    hi = h; lo = l;
}

#define MMA_TF32(c, a, b)                                                     \
    asm volatile(                                                             \
        "mma.sync.aligned.m16n8k8.row.col.f32.tf32.tf32.f32 "                 \
        "{%0,%1,%2,%3},{%4,%5,%6,%7},{%8,%9},{%0,%1,%2,%3};"                  \
        : "+f"(c[0]), "+f"(c[1]), "+f"(c[2]), "+f"(c[3])                      \
        : "r"(a[0]), "r"(a[1]), "r"(a[2]), "r"(a[3]), "r"(b[0]), "r"(b[1]))

__global__ __launch_bounds__(256, 1) void gemm_kernel(
        const float4* __restrict__ W4,    // [128*32] (k, j/4)
        const float*  __restrict__ bias,  // [128]
        float2* __restrict__ out2) {      // [N_NODES * 64]
    extern __shared__ float smem[];
    float* As  = smem;                       // [128][AS_STRIDE] fp32
    float* Whi = smem + 128 * AS_STRIDE;     // [128][WS_STRIDE] tf32-hi bits
    float* Wlo = Whi + 128 * WS_STRIDE;      // [128][WS_STRIDE] tf32-lo bits

    const int tid  = threadIdx.x;
    const int lane = tid & 31;
    const int w    = tid >> 5;
    const int quad = lane >> 2;   // 0..7
    const int tq   = lane & 3;    // 0..3
    const int wr   = w & 3;       // 32-row slab
    const int wc   = w >> 2;      // 64-col slab
    const int rowBase = blockIdx.x * 128;

    // ---- stage A (fp32) ----
#pragma unroll
    for (int p = 0; p < 16; p++) {
        int idx = p * 256 + tid;          // 0..4095
        int r = idx >> 5, c = idx & 31;
        float4 v = make_float4(0.f, 0.f, 0.f, 0.f);
        if (rowBase + r < N_NODES) v = g_pooled[(rowBase + r) * 32 + c];
        *reinterpret_cast<float4*>(As + r * AS_STRIDE + c * 4) = v;
    }
    // ---- stage W pre-split into hi/lo tf32 ----
#pragma unroll
    for (int p = 0; p < 16; p++) {
        int idx = p * 256 + tid;
        int k = idx >> 5, c = idx & 31;
        float4 v = __ldg(&W4[idx]);
        uint32_t h0, h1, h2, h3, l0, l1, l2, l3;
        tf32_split(v.x, h0, l0);
        tf32_split(v.y, h1, l1);
        tf32_split(v.z, h2, l2);
        tf32_split(v.w, h3, l3);
        float4 hv = make_float4(__uint_as_float(h0), __uint_as_float(h1),
                                __uint_as_float(h2), __uint_as_float(h3));
        float4 lv = make_float4(__uint_as_float(l0), __uint_as_float(l1),
                                __uint_as_float(l2), __uint_as_float(l3));
        *reinterpret_cast<float4*>(Whi + k * WS_STRIDE + c * 4) = hv;
        *reinterpret_cast<float4*>(Wlo + k * WS_STRIDE + c * 4) = lv;
    }
    __syncthreads();

    float acc[2][8][4];
#pragma unroll
    for (int s = 0; s < 2; s++)
#pragma unroll
        for (int nt = 0; nt < 8; nt++)
#pragma unroll
            for (int j = 0; j < 4; j++) acc[s][nt][j] = 0.f;

    const float* AsW  = As + wr * 32 * AS_STRIDE;
    const float* WhiW = Whi + wc * 64;
    const float* WloW = Wlo + wc * 64;

#pragma unroll 2
    for (int kt = 0; kt < 16; kt++) {
        const int k0 = kt * 8;
        // A fragments (fp32 -> split in regs)
        uint32_t ahi[2][4], alo[2][4];
#pragma unroll
        for (int s = 0; s < 2; s++) {
            float a0 = AsW[(s * 16 + quad) * AS_STRIDE + k0 + tq];
            float a1 = AsW[(s * 16 + quad + 8) * AS_STRIDE + k0 + tq];
            float a2 = AsW[(s * 16 + quad) * AS_STRIDE + k0 + tq + 4];
            float a3 = AsW[(s * 16 + quad + 8) * AS_STRIDE + k0 + tq + 4];
            tf32_split(a0, ahi[s][0], alo[s][0]);
            tf32_split(a1, ahi[s][1], alo[s][1]);
            tf32_split(a2, ahi[s][2], alo[s][2]);
            tf32_split(a3, ahi[s][3], alo[s][3]);
        }
        // B fragments (pre-split in smem)
        uint32_t bhi[8][2], blo[8][2];
#pragma unroll
        for (int nt = 0; nt < 8; nt++) {
            int coff = nt * 8 + quad;
            bhi[nt][0] = __float_as_uint(WhiW[(k0 + tq) * WS_STRIDE + coff]);
            bhi[nt][1] = __float_as_uint(WhiW[(k0 + tq + 4) * WS_STRIDE + coff]);
            blo[nt][0] = __float_as_uint(WloW[(k0 + tq) * WS_STRIDE + coff]);
            blo[nt][1] = __float_as_uint(WloW[(k0 + tq + 4) * WS_STRIDE + coff]);
        }
#pragma unroll
        for (int s = 0; s < 2; s++)
#pragma unroll
            for (int nt = 0; nt < 8; nt++) {
                MMA_TF32(acc[s][nt], ahi[s], bhi[nt]);
                MMA_TF32(acc[s][nt], ahi[s], blo[nt]);
                MMA_TF32(acc[s][nt], alo[s], bhi[nt]);
            }
    }

    // ---- epilogue: bias + relu, float2 stores ----
    const int colBase = wc * 64;
#pragma unroll
    for (int nt = 0; nt < 8; nt++) {
        int col = colBase + nt * 8 + 2 * tq;
        float2 bb = *reinterpret_cast<const float2*>(bias + col);
#pragma unroll
        for (int s = 0; s < 2; s++) {
            int r0 = rowBase + wr * 32 + s * 16 + quad;
            if (r0 < N_NODES) {
                float2 o;
                o.x = fmaxf(acc[s][nt][0] + bb.x, 0.f);
                o.y = fmaxf(acc[s][nt][1] + bb.y, 0.f);
                out2[r0 * 64 + (col >> 1)] = o;
            }
            if (r0 + 8 < N_NODES) {
                float2 o;
                o.x = fmaxf(acc[s][nt][2] + bb.x, 0.f);
                o.y = fmaxf(acc[s][nt][3] + bb.y, 0.f);
                out2[(r0 + 8) * 64 + (col >> 1)] = o;
            }
        }
    }
}

// ---------------------------------------------------------------------------
// Inputs: x [N,D] f32, source [E] i32, target [E] i32, W [D,U] f32, b [U] f32
// ---------------------------------------------------------------------------
extern "C" void kernel_launch(void* const* d_in, const int* in_sizes, int n_in,
                              void* d_out, int out_size) {
    const float4* x   = (const float4*)d_in[0];
    const int*    src = (const int*)d_in[1];
    const int*    tgt = (const int*)d_in[2];
    const float4* W4  = (const float4*)d_in[3];
    const float*  b   = (const float*)d_in[4];
    float2* out2 = (float2*)d_out;

    cudaFuncSetAttribute(gemm_kernel,
                         cudaFuncAttributeMaxDynamicSharedMemorySize, GEMM_SMEM);

    const int T = N_EDGES / 4;
    zero_kernel<<<128, 256>>>();
    hist_kernel<<<(T + 255) / 256, 256>>>(src, tgt);
    chunk_kernel<<<(N_NODES + 255) / 256, 256>>>();
    sort_kernel<<<(T + 255) / 256, 256>>>(src, tgt);
    gather_kernel<<<(N_NODES * 32 + 255) / 256, 256>>>(x);
    gemm_kernel<<<(N_NODES + 127) / 128, 256, GEMM_SMEM>>>(W4, b, out2);
}

// round 4
// speedup vs baseline: 1.6027x; 1.0282x over previous
#include <cuda_runtime.h>
#include <cuda_fp16.h>
#include <cstdint>

#define N_NODES 50000
#define D_FEAT  128
#define N_EDGES 800000
#define ROW_F4  32

// Scratch (__device__ globals — allocation-free rule)
__device__ float4 g_pooled[N_NODES * ROW_F4];   // 25.6 MB, GEMM input (fp32)
__device__ uint2  g_xh[N_NODES * ROW_F4];       // 12.8 MB, fp16 x * sender_scale
__device__ int    g_hist_out[N_NODES];
__device__ int    g_hist_in[N_NODES];
__device__ int    g_start[N_NODES];
__device__ int    g_cursor[N_NODES];
__device__ int    g_sorted_src[N_EDGES];
__device__ float  g_sscale[N_NODES];
__device__ int    g_counter;

// ---------------------------------------------------------------------------
// K0: zero histograms + chunk counter
// ---------------------------------------------------------------------------
__global__ void zero_kernel() {
    int i = blockIdx.x * blockDim.x + threadIdx.x;
    int stride = gridDim.x * blockDim.x;
    for (int j = i; j < N_NODES; j += stride) {
        g_hist_out[j] = 0;
        g_hist_in[j]  = 0;
    }
    if (i == 0) g_counter = 0;
}

// ---------------------------------------------------------------------------
// K1: degree histograms (4 edges/thread, REDG no-return)
// ---------------------------------------------------------------------------
__global__ void hist_kernel(const int* __restrict__ src,
                            const int* __restrict__ tgt) {
    const int T = N_EDGES / 4;
    int t = blockIdx.x * blockDim.x + threadIdx.x;
    if (t >= T) return;
#pragma unroll
    for (int u = 0; u < 4; u++) {
        int e = t + u * T;
        atomicAdd(&g_hist_out[__ldg(&src[e])], 1);
        atomicAdd(&g_hist_in[__ldg(&tgt[e])], 1);
    }
}

// ---------------------------------------------------------------------------
// K2: chunk assignment — warp-aggregated atomic grabs a contiguous slice of
// g_sorted_src per node (group order irrelevant). Also sender scales.
// ---------------------------------------------------------------------------
__global__ void chunk_kernel() {
    int i    = blockIdx.x * blockDim.x + threadIdx.x;
    int lane = threadIdx.x & 31;
    int deg  = (i < N_NODES) ? g_hist_in[i] : 0;

    int incl = deg;
#pragma unroll
    for (int o = 1; o < 32; o <<= 1) {
        int n = __shfl_up_sync(0xFFFFFFFFu, incl, o);
        if (lane >= o) incl += n;
    }
    int total = __shfl_sync(0xFFFFFFFFu, incl, 31);
    int base = 0;
    if (lane == 31) base = atomicAdd(&g_counter, total);
    base = __shfl_sync(0xFFFFFFFFu, base, 31);

    if (i < N_NODES) {
        int st = base + incl - deg;
        g_start[i]  = st;
        g_cursor[i] = st;
        g_sscale[i] = rsqrtf(fmaxf((float)g_hist_out[i], 1.0f));
    }
}

// ---------------------------------------------------------------------------
// K2b: convert x -> fp16 with sender scale folded (halves gather L2 traffic)
// ---------------------------------------------------------------------------
__global__ __launch_bounds__(256) void convert_kernel(
        const float4* __restrict__ x) {
    int i = blockIdx.x * blockDim.x + threadIdx.x;
    if (i >= N_NODES * ROW_F4) return;
    float  s = __ldg(&g_sscale[i >> 5]);
    float4 v = __ldg(&x[i]);
    __half2 lo = __floats2half2_rn(v.x * s, v.y * s);
    __half2 hi = __floats2half2_rn(v.z * s, v.w * s);
    uint2 p;
    p.x = *reinterpret_cast<uint32_t*>(&lo);
    p.y = *reinterpret_cast<uint32_t*>(&hi);
    g_xh[i] = p;
}

// ---------------------------------------------------------------------------
// K3: counting-sort scatter, 8 independent edges per thread (MLP=8)
// ---------------------------------------------------------------------------
__global__ void sort_kernel(const int* __restrict__ src,
                            const int* __restrict__ tgt) {
    const int T = N_EDGES / 8;
    int t = blockIdx.x * blockDim.x + threadIdx.x;
    if (t >= T) return;
    int tg[8], sv[8], p[8];
#pragma unroll
    for (int u = 0; u < 8; u++) {
        tg[u] = __ldg(&tgt[t + u * T]);
        sv[u] = __ldg(&src[t + u * T]);
    }
#pragma unroll
    for (int u = 0; u < 8; u++) p[u] = atomicAdd(&g_cursor[tg[u]], 1);
#pragma unroll
    for (int u = 0; u < 8; u++) g_sorted_src[p[u]] = sv[u];
}

// ---------------------------------------------------------------------------
// K4: per-node gather-accumulate over fp16 rows. One warp per target node,
// lane owns 4 halfs (8B). Accumulate fp32; receiver scale on the one write.
// ---------------------------------------------------------------------------
__global__ __launch_bounds__(256) void gather_kernel() {
    int t    = (blockIdx.x * blockDim.x + threadIdx.x) >> 5;
    int lane = threadIdx.x & 31;
    if (t >= N_NODES) return;

    int start = __ldg(&g_start[t]);
    int deg   = __ldg(&g_hist_in[t]);

    float4 acc = make_float4(0.f, 0.f, 0.f, 0.f);
#pragma unroll 4
    for (int j = start; j < start + deg; ++j) {
        int   s = __ldg(&g_sorted_src[j]);      // warp-uniform broadcast
        uint2 e = __ldg(&g_xh[s * ROW_F4 + lane]);
        __half2 h0 = *reinterpret_cast<__half2*>(&e.x);
        __half2 h1 = *reinterpret_cast<__half2*>(&e.y);
        float2 f0 = __half22float2(h0);
        float2 f1 = __half22float2(h1);
        acc.x += f0.x; acc.y += f0.y;
        acc.z += f1.x; acc.w += f1.y;
    }
    float rsc = rsqrtf(fmaxf((float)deg, 1.0f));
    acc.x *= rsc; acc.y *= rsc; acc.z *= rsc; acc.w *= rsc;
    g_pooled[t * ROW_F4 + lane] = acc;
}

// ---------------------------------------------------------------------------
// K5: out = relu( pooled @ W + b ) via tf32 mma.sync, 3-term split:
//   D = Ahi@Whi + Ahi@Wlo + Alo@Whi
// 256 thr, 128x128 tile, full K=128 smem-resident, warp tile 32x64.
// ---------------------------------------------------------------------------
#define AS_STRIDE 132
#define WS_STRIDE 136
#define GEMM_SMEM ((128 * AS_STRIDE + 2 * 128 * WS_STRIDE) * (int)sizeof(float))

__device__ __forceinline__ void tf32_split(float a, uint32_t& hi, uint32_t& lo) {
    uint32_t h;
    asm("cvt.rna.tf32.f32 %0, %1;" : "=r"(h) : "f"(a));
    float r = a - __uint_as_float(h);
    uint32_t l;
    asm("cvt.rna.tf32.f32 %0, %1;" : "=r"(l) : "f"(r));
    hi = h; lo = l;
}

#define MMA_TF32(c, a, b)                                                     \
    asm volatile(                                                             \
        "mma.sync.aligned.m16n8k8.row.col.f32.tf32.tf32.f32 "                 \
        "{%0,%1,%2,%3},{%4,%5,%6,%7},{%8,%9},{%0,%1,%2,%3};"                  \
        : "+f"(c[0]), "+f"(c[1]), "+f"(c[2]), "+f"(c[3])                      \
        : "r"(a[0]), "r"(a[1]), "r"(a[2]), "r"(a[3]), "r"(b[0]), "r"(b[1]))

__global__ __launch_bounds__(256, 1) void gemm_kernel(
        const float4* __restrict__ W4,    // [128*32] (k, j/4)
        const float*  __restrict__ bias,  // [128]
        float2* __restrict__ out2) {      // [N_NODES * 64]
    extern __shared__ float smem[];
    float* As  = smem;                       // [128][AS_STRIDE]
    float* Whi = smem + 128 * AS_STRIDE;     // [128][WS_STRIDE]
    float* Wlo = Whi + 128 * WS_STRIDE;      // [128][WS_STRIDE]

    const int tid  = threadIdx.x;
    const int lane = tid & 31;
    const int w    = tid >> 5;
    const int quad = lane >> 2;
    const int tq   = lane & 3;
    const int wr   = w & 3;
    const int wc   = w >> 2;
    const int rowBase = blockIdx.x * 128;

#pragma unroll
    for (int p = 0; p < 16; p++) {
        int idx = p * 256 + tid;
        int r = idx >> 5, c = idx & 31;
        float4 v = make_float4(0.f, 0.f, 0.f, 0.f);
        if (rowBase + r < N_NODES) v = g_pooled[(rowBase + r) * 32 + c];
        *reinterpret_cast<float4*>(As + r * AS_STRIDE + c * 4) = v;
    }
#pragma unroll
    for (int p = 0; p < 16; p++) {
        int idx = p * 256 + tid;
        int k = idx >> 5, c = idx & 31;
        float4 v = __ldg(&W4[idx]);
        uint32_t h0, h1, h2, h3, l0, l1, l2, l3;
        tf32_split(v.x, h0, l0);
        tf32_split(v.y, h1, l1);
        tf32_split(v.z, h2, l2);
        tf32_split(v.w, h3, l3);
        float4 hv = make_float4(__uint_as_float(h0), __uint_as_float(h1),
                                __uint_as_float(h2), __uint_as_float(h3));
        float4 lv = make_float4(__uint_as_float(l0), __uint_as_float(l1),
                                __uint_as_float(l2), __uint_as_float(l3));
        *reinterpret_cast<float4*>(Whi + k * WS_STRIDE + c * 4) = hv;
        *reinterpret_cast<float4*>(Wlo + k * WS_STRIDE + c * 4) = lv;
    }
    __syncthreads();

    float acc[2][8][4];
#pragma unroll
    for (int s = 0; s < 2; s++)
#pragma unroll
        for (int nt = 0; nt < 8; nt++)
#pragma unroll
            for (int j = 0; j < 4; j++) acc[s][nt][j] = 0.f;

    const float* AsW  = As + wr * 32 * AS_STRIDE;
    const float* WhiW = Whi + wc * 64;
    const float* WloW = Wlo + wc * 64;

#pragma unroll 2
    for (int kt = 0; kt < 16; kt++) {
        const int k0 = kt * 8;
        uint32_t ahi[2][4], alo[2][4];
#pragma unroll
        for (int s = 0; s < 2; s++) {
            float a0 = AsW[(s * 16 + quad) * AS_STRIDE + k0 + tq];
            float a1 = AsW[(s * 16 + quad + 8) * AS_STRIDE + k0 + tq];
            float a2 = AsW[(s * 16 + quad) * AS_STRIDE + k0 + tq + 4];
            float a3 = AsW[(s * 16 + quad + 8) * AS_STRIDE + k0 + tq + 4];
            tf32_split(a0, ahi[s][0], alo[s][0]);
            tf32_split(a1, ahi[s][1], alo[s][1]);
            tf32_split(a2, ahi[s][2], alo[s][2]);
            tf32_split(a3, ahi[s][3], alo[s][3]);
        }
        uint32_t bhi[8][2], blo[8][2];
#pragma unroll
        for (int nt = 0; nt < 8; nt++) {
            int coff = nt * 8 + quad;
            bhi[nt][0] = __float_as_uint(WhiW[(k0 + tq) * WS_STRIDE + coff]);
            bhi[nt][1] = __float_as_uint(WhiW[(k0 + tq + 4) * WS_STRIDE + coff]);
            blo[nt][0] = __float_as_uint(WloW[(k0 + tq) * WS_STRIDE + coff]);
            blo[nt][1] = __float_as_uint(WloW[(k0 + tq + 4) * WS_STRIDE + coff]);
        }
#pragma unroll
        for (int s = 0; s < 2; s++)
#pragma unroll
            for (int nt = 0; nt < 8; nt++) {
                MMA_TF32(acc[s][nt], ahi[s], bhi[nt]);
                MMA_TF32(acc[s][nt], ahi[s], blo[nt]);
                MMA_TF32(acc[s][nt], alo[s], bhi[nt]);
            }
    }

    const int colBase = wc * 64;
#pragma unroll
    for (int nt = 0; nt < 8; nt++) {
        int col = colBase + nt * 8 + 2 * tq;
        float2 bb = *reinterpret_cast<const float2*>(bias + col);
#pragma unroll
        for (int s = 0; s < 2; s++) {
            int r0 = rowBase + wr * 32 + s * 16 + quad;
            if (r0 < N_NODES) {
                float2 o;
                o.x = fmaxf(acc[s][nt][0] + bb.x, 0.f);
                o.y = fmaxf(acc[s][nt][1] + bb.y, 0.f);
                out2[r0 * 64 + (col >> 1)] = o;
            }
            if (r0 + 8 < N_NODES) {
                float2 o;
                o.x = fmaxf(acc[s][nt][2] + bb.x, 0.f);
                o.y = fmaxf(acc[s][nt][3] + bb.y, 0.f);
                out2[(r0 + 8) * 64 + (col >> 1)] = o;
            }
        }
    }
}

// ---------------------------------------------------------------------------
// Inputs: x [N,D] f32, source [E] i32, target [E] i32, W [D,U] f32, b [U] f32
// ---------------------------------------------------------------------------
extern "C" void kernel_launch(void* const* d_in, const int* in_sizes, int n_in,
                              void* d_out, int out_size) {
    const float4* x   = (const float4*)d_in[0];
    const int*    src = (const int*)d_in[1];
    const int*    tgt = (const int*)d_in[2];
    const float4* W4  = (const float4*)d_in[3];
    const float*  b   = (const float*)d_in[4];
    float2* out2 = (float2*)d_out;

    cudaFuncSetAttribute(gemm_kernel,
                         cudaFuncAttributeMaxDynamicSharedMemorySize, GEMM_SMEM);

    zero_kernel<<<128, 256>>>();
    hist_kernel<<<(N_EDGES / 4 + 255) / 256, 256>>>(src, tgt);
    chunk_kernel<<<(N_NODES + 255) / 256, 256>>>();
    convert_kernel<<<(N_NODES * ROW_F4 + 255) / 256, 256>>>(x);
    sort_kernel<<<(N_EDGES / 8 + 255) / 256, 256>>>(src, tgt);
    gather_kernel<<<(N_NODES * 32 + 255) / 256, 256>>>();
    gemm_kernel<<<(N_NODES + 127) / 128, 256, GEMM_SMEM>>>(W4, b, out2);
}